// round 15
// baseline (speedup 1.0000x reference)
#include <cuda_runtime.h>

#define BB 4
#define NN 128
#define DD 128
#define EPS 1e-6f

// scratch for x = dense2(glu(dense1(rmsnorm(q))))  : (B, N, 3D) floats
__device__ float g_x[BB * NN * 3 * DD];

// ---------------------------------------------------------------------------
// Phase A: per-row RMSNorm -> GEMM1 (D->2D) -> GLU -> GEMM2 (D->3D) -> g_x
// Also initializes out with q / mu (phaseB accumulates into out atomically).
// 4 rows per block, 256 threads, thread-per-output GEMV. Grid = 128 blocks.
// (Proven fastest phaseA variant; unchanged from round 14.)
// ---------------------------------------------------------------------------
__global__ __launch_bounds__(256) void phaseA_kernel(
    const float* __restrict__ q,
    const float* __restrict__ mu,
    const float* __restrict__ norm_w,
    const float* __restrict__ W1,
    const float* __restrict__ b1,
    const float* __restrict__ W2,
    const float* __restrict__ b2,
    float* __restrict__ out)
{
    __shared__ float hs[4][DD];     // normed input
    __shared__ float ys[4][2 * DD]; // GEMM1 output
    __shared__ float h2s[4][DD];    // GLU output
    __shared__ float rms[4];

    const int tid = threadIdx.x;
    const int row0 = blockIdx.x * 4;   // global row = b*N + n

    // init out with q and mu (phaseB adds dq/dmu via atomics)
    {
        const float4* qs = (const float4*)(q) + row0 * (DD / 4);
        float4* oq = (float4*)(out) + row0 * (DD / 4);
        for (int c = tid; c < 4 * (DD / 4); c += 256) oq[c] = qs[c];
        const float4* ms = (const float4*)(mu) + row0 * (3 * DD / 4);
        float4* om = (float4*)(out + BB * NN * DD) + row0 * (3 * DD / 4);
        for (int c = tid; c < 4 * (3 * DD / 4); c += 256) om[c] = ms[c];
    }

    // load q rows into smem
    if (tid < DD) {
        #pragma unroll
        for (int r = 0; r < 4; r++)
            hs[r][tid] = q[(row0 + r) * DD + tid];
    }
    __syncthreads();

    // per-row sum of squares (warp r reduces row r)
    const int w = tid >> 5, l = tid & 31;
    if (w < 4) {
        float s = 0.f;
        #pragma unroll
        for (int c = l; c < DD; c += 32) { float v = hs[w][c]; s += v * v; }
        #pragma unroll
        for (int o = 16; o; o >>= 1) s += __shfl_xor_sync(0xffffffffu, s, o);
        if (l == 0) rms[w] = rsqrtf(s * (1.0f / DD) + EPS);
    }
    __syncthreads();

    if (tid < DD) {
        const float nw = 1.0f + norm_w[tid];
        #pragma unroll
        for (int r = 0; r < 4; r++)
            hs[r][tid] *= rms[r] * nw;
    }
    __syncthreads();

    // GEMM1: y[r][o] = b1[o] + sum_d hs[r][d] * W1[o][d]   (o = tid in [0,256))
    {
        const int o = tid;
        float a0 = b1[o], a1 = a0, a2 = a0, a3 = a0;
        const float4* wrow = (const float4*)(W1) + o * (DD / 4);
        const float4* h0 = (const float4*)hs[0];
        const float4* h1 = (const float4*)hs[1];
        const float4* h2 = (const float4*)hs[2];
        const float4* h3 = (const float4*)hs[3];
        #pragma unroll
        for (int d4 = 0; d4 < DD / 4; d4++) {
            float4 wv = __ldg(wrow + d4);
            float4 v;
            v = h0[d4]; a0 += wv.x*v.x + wv.y*v.y + wv.z*v.z + wv.w*v.w;
            v = h1[d4]; a1 += wv.x*v.x + wv.y*v.y + wv.z*v.z + wv.w*v.w;
            v = h2[d4]; a2 += wv.x*v.x + wv.y*v.y + wv.z*v.z + wv.w*v.w;
            v = h3[d4]; a3 += wv.x*v.x + wv.y*v.y + wv.z*v.z + wv.w*v.w;
        }
        ys[0][o] = a0; ys[1][o] = a1; ys[2][o] = a2; ys[3][o] = a3;
    }
    __syncthreads();

    // GLU: h2 = silu(a) * sigmoid(g)
    if (tid < DD) {
        #pragma unroll
        for (int r = 0; r < 4; r++) {
            float a = ys[r][tid];
            float g = ys[r][tid + DD];
            float sa = 1.0f / (1.0f + __expf(-a));
            float sg = 1.0f / (1.0f + __expf(-g));
            h2s[r][tid] = a * sa * sg;
        }
    }
    __syncthreads();

    // GEMM2: x[r][c] = b2[c] + sum_d h2s[r][d] * W2[c][d], c in [0,384)
    for (int c = tid; c < 3 * DD; c += 256) {
        float a0 = b2[c], a1 = a0, a2 = a0, a3 = a0;
        const float4* wrow = (const float4*)(W2) + c * (DD / 4);
        const float4* h0 = (const float4*)h2s[0];
        const float4* h1 = (const float4*)h2s[1];
        const float4* h2 = (const float4*)h2s[2];
        const float4* h3 = (const float4*)h2s[3];
        #pragma unroll
        for (int d4 = 0; d4 < DD / 4; d4++) {
            float4 wv = __ldg(wrow + d4);
            float4 v;
            v = h0[d4]; a0 += wv.x*v.x + wv.y*v.y + wv.z*v.z + wv.w*v.w;
            v = h1[d4]; a1 += wv.x*v.x + wv.y*v.y + wv.z*v.z + wv.w*v.w;
            v = h2[d4]; a2 += wv.x*v.x + wv.y*v.y + wv.z*v.z + wv.w*v.w;
            v = h3[d4]; a3 += wv.x*v.x + wv.y*v.y + wv.z*v.z + wv.w*v.w;
        }
        g_x[(row0 + 0) * 3 * DD + c] = a0;
        g_x[(row0 + 1) * 3 * DD + c] = a1;
        g_x[(row0 + 2) * 3 * DD + c] = a2;
        g_x[(row0 + 3) * 3 * DD + c] = a3;
    }
}

// ---------------------------------------------------------------------------
// Phase B: pairwise accumulation, 5-stage cp.async ring, 1 j per stage.
// Block = (b, 4-i tile, 32-j tile). Grid = 512, 256 threads.
// NEW thread mapping: thread t -> (jq = t>>6, co = t&63).
//   Group jq (2 warps) consumes stages s with s % 4 == jq and computes ALL
//   4 il rows for its float2 channel slot co -> x/mu read from smem ONCE
//   per j (was x4), halving crossbar traffic. Accums: 4 il x 8 floats.
// Epilogue: jq-partials reduced via sStage scratch, then atomicAdd.
// Ring safety unchanged: issue(s+4) targets slot (s-1)%5, whose consumers
// finished before the barrier at the top of iteration s.
// ---------------------------------------------------------------------------
#define SJ_F4 576
#define SJ_BYTES 9216
#define NSTG 5

__device__ __forceinline__ void cp16(unsigned int dst, const void* src) {
    asm volatile("cp.async.cg.shared.global [%0], [%1], 16;" :: "r"(dst), "l"(src));
}

__global__ __launch_bounds__(256, 3) void phaseB_kernel(
    const float* __restrict__ mu,
    const float* __restrict__ Wij,
    const float* __restrict__ dir_ij,
    const float* __restrict__ mask_ij,
    float* __restrict__ out)
{
    __shared__ float4 sStage[NSTG][SJ_F4];   // 46080 B (reused for reduction)
    __shared__ float smsk[4][32];            // 512 B
    __shared__ float sdir[4][32][3];         // 1536 B

    const int tid = threadIdx.x;
    const int it = blockIdx.x & 31;
    const int b  = (blockIdx.x >> 5) & 3;
    const int jt = blockIdx.x >> 7;
    const int i0 = it * 4;
    const int jb0 = jt * 32;
    const int jq = tid >> 6;      // stage group (0..3)
    const int co = tid & 63;      // float2 channel slot (0..63)

    // --- stage mask / dir into smem (visible after first barrier) ---
    if (tid < 128) {
        int mil = tid >> 5, jl = tid & 31;
        smsk[mil][jl] = __ldg(mask_ij + (b * NN + i0 + mil) * NN + jb0 + jl);
    }
    for (int e = tid; e < 384; e += 256) {
        int mil = e / 96, r = e % 96;
        int jl = r / 3, k = r % 3;
        sdir[mil][jl][k] = __ldg(dir_ij + ((b * NN + i0 + mil) * NN + jb0 + jl) * 3 + k);
    }

    // --- per-thread cp.async slots (all sources advance by 96 f4 per j) ---
    const float4* Wf4  = (const float4*)Wij;
    const float4* xf4  = (const float4*)g_x;
    const float4* muf4 = (const float4*)mu;
    const float4* slotSrc[3];
    unsigned int slotDst[3];
    unsigned int sbase = (unsigned int)__cvta_generic_to_shared(&sStage[0][0]);
    #pragma unroll
    for (int k = 0; k < 3; k++) {
        int e = tid + k * 256;
        const float4* src = 0;
        if (e < SJ_F4) {
            if (e < 384) {
                src = Wf4 + ((size_t)(b * NN + i0 + e / 96) * NN + jb0) * 96 + (e % 96);
            } else if (e < 480) {
                src = xf4 + (size_t)(b * NN + jb0) * 96 + (e - 384);
            } else {
                src = muf4 + (size_t)(b * NN + jb0) * 96 + (e - 480);
            }
        }
        slotSrc[k] = src;
        slotDst[k] = sbase + (unsigned int)e * 16u;
    }
    const bool slot2 = (tid < 64);

#define ISSUE_STAGE(s)                                                   \
    {                                                                    \
        const unsigned int bo = ((s) % NSTG) * (unsigned int)SJ_BYTES;   \
        const int adv = (s) * 96;                                        \
        cp16(slotDst[0] + bo, slotSrc[0] + adv);                         \
        cp16(slotDst[1] + bo, slotSrc[1] + adv);                         \
        if (slot2) cp16(slotDst[2] + bo, slotSrc[2] + adv);              \
        asm volatile("cp.async.commit_group;" ::: "memory");             \
    }

    ISSUE_STAGE(0)
    ISSUE_STAGE(1)
    ISSUE_STAGE(2)
    ISSUE_STAGE(3)

    // accumulators: per il row, {accq, am0, am1, am2} as float2
    float2 Aq[4], A0[4], A1[4], A2[4];
    #pragma unroll
    for (int il = 0; il < 4; il++) {
        Aq[il] = make_float2(0.f, 0.f);
        A0[il] = Aq[il]; A1[il] = Aq[il]; A2[il] = Aq[il];
    }

    for (int s = 0; s < 32; s++) {
        if (s <= 28)      asm volatile("cp.async.wait_group 3;" ::: "memory");
        else if (s == 29) asm volatile("cp.async.wait_group 2;" ::: "memory");
        else if (s == 30) asm volatile("cp.async.wait_group 1;" ::: "memory");
        else              asm volatile("cp.async.wait_group 0;" ::: "memory");
        __syncthreads();

        if (((s - jq) & 3) == 0) {
            const float2* stg2 = (const float2*)&sStage[s % NSTG][0];
            // x/mu: loaded ONCE for this j
            float2 xq = stg2[768 + co];
            float2 xr = stg2[832 + co];
            float2 xm = stg2[896 + co];
            float2 m0 = stg2[960 + co];
            float2 m1 = stg2[1024 + co];
            float2 m2 = stg2[1088 + co];

            #pragma unroll
            for (int il = 0; il < 4; il++) {
                const float m  = smsk[il][s];       // broadcast LDS
                const float d0 = sdir[il][s][0];
                const float d1 = sdir[il][s][1];
                const float d2 = sdir[il][s][2];
                float2 wq = stg2[il * 192 + co];
                float2 wr = stg2[il * 192 + 64 + co];
                float2 wm = stg2[il * 192 + 128 + co];

#define PAINN_COMP(c)                                                   \
                {                                                       \
                    Aq[il].c = fmaf(wq.c * xq.c, m, Aq[il].c);          \
                    float t = wr.c * xr.c * m;                          \
                    A0[il].c = fmaf(t, d0, A0[il].c);                   \
                    A1[il].c = fmaf(t, d1, A1[il].c);                   \
                    A2[il].c = fmaf(t, d2, A2[il].c);                   \
                    t = wm.c * xm.c * m;                                \
                    A0[il].c = fmaf(t, m0.c, A0[il].c);                 \
                    A1[il].c = fmaf(t, m1.c, A1[il].c);                 \
                    A2[il].c = fmaf(t, m2.c, A2[il].c);                 \
                }
                PAINN_COMP(x)
                PAINN_COMP(y)
#undef PAINN_COMP
            }
        }

        if (s < 28) ISSUE_STAGE(s + 4)
    }
#undef ISSUE_STAGE

    // --- reduce jq-partials through smem (sStage is dead now) ---
    __syncthreads();   // all consumption done; safe to overwrite sStage
    float4* sRed = (float4*)&sStage[0][0];   // 16*64*2 f4 = 32 KB < 45 KB
    #pragma unroll
    for (int il = 0; il < 4; il++) {
        int idx = ((jq * 4 + il) * 64 + co) * 2;
        sRed[idx]     = make_float4(Aq[il].x, Aq[il].y, A0[il].x, A0[il].y);
        sRed[idx + 1] = make_float4(A1[il].x, A1[il].y, A2[il].x, A2[il].y);
    }
    __syncthreads();

    {
        const int il2 = tid >> 6, co2 = tid & 63;
        float4 r0 = make_float4(0.f, 0.f, 0.f, 0.f), r1 = r0;
        #pragma unroll
        for (int g = 0; g < 4; g++) {
            int idx = ((g * 4 + il2) * 64 + co2) * 2;
            float4 a = sRed[idx], c = sRed[idx + 1];
            r0.x += a.x; r0.y += a.y; r0.z += a.z; r0.w += a.w;
            r1.x += c.x; r1.y += c.y; r1.z += c.z; r1.w += c.w;
        }
        const int bio = b * NN + i0 + il2;
        const int c0 = 2 * co2;
        float* oq = out + bio * DD + c0;
        atomicAdd(oq + 0, r0.x);
        atomicAdd(oq + 1, r0.y);
        float* om = out + BB * NN * DD + bio * 3 * DD + c0;
        atomicAdd(om + 0,          r0.z);
        atomicAdd(om + 1,          r0.w);
        atomicAdd(om + DD + 0,     r1.x);
        atomicAdd(om + DD + 1,     r1.y);
        atomicAdd(om + 2 * DD + 0, r1.z);
        atomicAdd(om + 2 * DD + 1, r1.w);
    }
}

// ---------------------------------------------------------------------------
extern "C" void kernel_launch(void* const* d_in, const int* in_sizes, int n_in,
                              void* d_out, int out_size)
{
    const float* q       = (const float*)d_in[0];
    const float* mu      = (const float*)d_in[1];
    const float* Wij     = (const float*)d_in[2];
    const float* dir_ij  = (const float*)d_in[3];
    const float* mask_ij = (const float*)d_in[4];
    const float* norm_w  = (const float*)d_in[5];
    const float* W1      = (const float*)d_in[6];
    const float* b1      = (const float*)d_in[7];
    const float* W2      = (const float*)d_in[8];
    const float* b2      = (const float*)d_in[9];
    float* out = (float*)d_out;

    phaseA_kernel<<<(BB * NN) / 4, 256>>>(q, mu, norm_w, W1, b1, W2, b2, out);
    phaseB_kernel<<<BB * NN, 256>>>(mu, Wij, dir_ij, mask_ij, out);
}

// round 16
// speedup vs baseline: 1.1237x; 1.1237x over previous
#include <cuda_runtime.h>

#define BB 4
#define NN 128
#define DD 128
#define EPS 1e-6f

// scratch for x = dense2(glu(dense1(rmsnorm(q))))  : (B, N, 3D) floats
__device__ float g_x[BB * NN * 3 * DD];

// ---------------------------------------------------------------------------
// Phase A: per-row RMSNorm -> GEMM1 (D->2D) -> GLU -> GEMM2 (D->3D) -> g_x
// Also initializes out with q / mu (phaseB accumulates into out atomically).
// 4 rows per block, 512 threads = 16 warps. Grid = 128 blocks.
// WARP-PER-OUTPUT GEMV: lane l holds W[o][4l..4l+3] (one coalesced LDG.128
// per output), h vectors hoisted to registers, butterfly reduction.
// ---------------------------------------------------------------------------
__global__ __launch_bounds__(512) void phaseA_kernel(
    const float* __restrict__ q,
    const float* __restrict__ mu,
    const float* __restrict__ norm_w,
    const float* __restrict__ W1,
    const float* __restrict__ b1,
    const float* __restrict__ W2,
    const float* __restrict__ b2,
    float* __restrict__ out)
{
    __shared__ float hs[4][DD];      // normed input
    __shared__ float ys[4][2 * DD];  // GEMM1 output
    __shared__ float h2s[4][DD];     // GLU output
    __shared__ float xs[4][3 * DD];  // GEMM2 staging for coalesced store
    __shared__ float rms[4];

    const int tid = threadIdx.x;
    const int row0 = blockIdx.x * 4;
    const int w = tid >> 5, l = tid & 31;

    // init out with q and mu (phaseB adds dq/dmu via atomics)
    if (tid < 128)
        ((float4*)out)[row0 * 32 + tid] = ((const float4*)q)[row0 * 32 + tid];
    if (tid < 384)
        ((float4*)(out + BB * NN * DD))[row0 * 96 + tid] =
            ((const float4*)mu)[row0 * 96 + tid];

    // load q rows into smem (one element per thread)
    {
        int r = tid >> 7, c = tid & 127;
        hs[r][c] = q[(row0 + r) * DD + c];
    }
    __syncthreads();

    // per-row sum of squares (warps 0..3)
    if (w < 4) {
        float s = 0.f;
        #pragma unroll
        for (int c = l; c < DD; c += 32) { float v = hs[w][c]; s += v * v; }
        #pragma unroll
        for (int o = 16; o; o >>= 1) s += __shfl_xor_sync(0xffffffffu, s, o);
        if (l == 0) rms[w] = rsqrtf(s * (1.0f / DD) + EPS);
    }
    __syncthreads();

    {
        int r = tid >> 7, c = tid & 127;
        hs[r][c] *= rms[r] * (1.0f + __ldg(norm_w + c));
    }
    __syncthreads();

#define WREDUCE4()                                                       \
    {                                                                    \
        _Pragma("unroll")                                                \
        for (int off = 16; off; off >>= 1) {                             \
            a0 += __shfl_xor_sync(0xffffffffu, a0, off);                 \
            a1 += __shfl_xor_sync(0xffffffffu, a1, off);                 \
            a2 += __shfl_xor_sync(0xffffffffu, a2, off);                 \
            a3 += __shfl_xor_sync(0xffffffffu, a3, off);                 \
        }                                                                \
    }

    // GEMM1: 256 outputs, warp w handles o in [w*16, w*16+16).
    {
        // hoist h vectors: lane l's K-slice for all 4 rows
        const float4 v0 = ((const float4*)hs[0])[l];
        const float4 v1 = ((const float4*)hs[1])[l];
        const float4 v2 = ((const float4*)hs[2])[l];
        const float4 v3 = ((const float4*)hs[3])[l];
        #pragma unroll 4
        for (int p = 0; p < 16; p++) {
            const int o = (w << 4) + p;
            const float4 wv = __ldg((const float4*)W1 + o * 32 + l);
            float a0 = wv.x*v0.x + wv.y*v0.y + wv.z*v0.z + wv.w*v0.w;
            float a1 = wv.x*v1.x + wv.y*v1.y + wv.z*v1.z + wv.w*v1.w;
            float a2 = wv.x*v2.x + wv.y*v2.y + wv.z*v2.z + wv.w*v2.w;
            float a3 = wv.x*v3.x + wv.y*v3.y + wv.z*v3.z + wv.w*v3.w;
            WREDUCE4()
            if (l == 0) {
                const float bb = __ldg(b1 + o);
                ys[0][o] = a0 + bb; ys[1][o] = a1 + bb;
                ys[2][o] = a2 + bb; ys[3][o] = a3 + bb;
            }
        }
    }
    __syncthreads();

    // GLU: h2 = silu(a) * sigmoid(g)   (512 elems, one per thread)
    {
        int r = tid >> 7, c = tid & 127;
        float a = ys[r][c];
        float g = ys[r][c + DD];
        float sa = 1.0f / (1.0f + __expf(-a));
        float sg = 1.0f / (1.0f + __expf(-g));
        h2s[r][c] = a * sa * sg;
    }
    __syncthreads();

    // GEMM2: 384 outputs, warp w handles o in [w*24, w*24+24).
    {
        const float4 v0 = ((const float4*)h2s[0])[l];
        const float4 v1 = ((const float4*)h2s[1])[l];
        const float4 v2 = ((const float4*)h2s[2])[l];
        const float4 v3 = ((const float4*)h2s[3])[l];
        #pragma unroll 4
        for (int p = 0; p < 24; p++) {
            const int o = w * 24 + p;
            const float4 wv = __ldg((const float4*)W2 + o * 32 + l);
            float a0 = wv.x*v0.x + wv.y*v0.y + wv.z*v0.z + wv.w*v0.w;
            float a1 = wv.x*v1.x + wv.y*v1.y + wv.z*v1.z + wv.w*v1.w;
            float a2 = wv.x*v2.x + wv.y*v2.y + wv.z*v2.z + wv.w*v2.w;
            float a3 = wv.x*v3.x + wv.y*v3.y + wv.z*v3.z + wv.w*v3.w;
            WREDUCE4()
            if (l == 0) {
                const float bb = __ldg(b2 + o);
                xs[0][o] = a0 + bb; xs[1][o] = a1 + bb;
                xs[2][o] = a2 + bb; xs[3][o] = a3 + bb;
            }
        }
    }
#undef WREDUCE4
    __syncthreads();

    // coalesced store of x to g_x (384 f4)
    if (tid < 384) {
        int r = tid / 96, c = tid % 96;
        ((float4*)g_x)[(row0 + r) * 96 + c] = ((const float4*)xs[r])[c];
    }
}

// ---------------------------------------------------------------------------
// Phase B: pairwise accumulation, 5-stage cp.async ring, 1 j per stage.
// (Byte-for-byte the proven round-14 version: 24.0 us, DRAM 57%.)
// Block = (b, 4-i tile, 32-j tile). Grid = 512, 256 threads = 8 warps:
//   warp w: il = w & 3 (row), h = w >> 2 (channel half: 64 channels).
//   lane l owns channels [h*64 + 2l, h*64 + 2l + 1] (float2 granularity).
// ---------------------------------------------------------------------------
#define SJ_F4 576
#define SJ_BYTES 9216
#define NSTG 5

__device__ __forceinline__ void cp16(unsigned int dst, const void* src) {
    asm volatile("cp.async.cg.shared.global [%0], [%1], 16;" :: "r"(dst), "l"(src));
}

__global__ __launch_bounds__(256, 4) void phaseB_kernel(
    const float* __restrict__ mu,
    const float* __restrict__ Wij,
    const float* __restrict__ dir_ij,
    const float* __restrict__ mask_ij,
    float* __restrict__ out)
{
    __shared__ float4 sStage[NSTG][SJ_F4];   // 46080 B
    __shared__ float smsk[4][32];            // 512 B
    __shared__ float sdir[4][32][3];         // 1536 B

    const int tid = threadIdx.x;
    const int w = tid >> 5, l = tid & 31;
    const int it = blockIdx.x & 31;
    const int b  = (blockIdx.x >> 5) & 3;
    const int jt = blockIdx.x >> 7;
    const int i0 = it * 4;
    const int il = w & 3;
    const int h  = w >> 2;
    const int jb0 = jt * 32;

    // --- stage mask / dir into smem (visible after first barrier) ---
    if (tid < 128) {
        int mil = tid >> 5, jl = tid & 31;
        smsk[mil][jl] = __ldg(mask_ij + (b * NN + i0 + mil) * NN + jb0 + jl);
    }
    for (int e = tid; e < 384; e += 256) {
        int mil = e / 96, r = e % 96;
        int jl = r / 3, k = r % 3;
        sdir[mil][jl][k] = __ldg(dir_ij + ((b * NN + i0 + mil) * NN + jb0 + jl) * 3 + k);
    }

    // --- per-thread cp.async slots (all sources advance by 96 f4 per j) ---
    const float4* Wf4  = (const float4*)Wij;
    const float4* xf4  = (const float4*)g_x;
    const float4* muf4 = (const float4*)mu;
    const float4* slotSrc[3];
    unsigned int slotDst[3];
    unsigned int sbase = (unsigned int)__cvta_generic_to_shared(&sStage[0][0]);
    #pragma unroll
    for (int k = 0; k < 3; k++) {
        int e = tid + k * 256;
        const float4* src = 0;
        if (e < SJ_F4) {
            if (e < 384) {
                src = Wf4 + ((size_t)(b * NN + i0 + e / 96) * NN + jb0) * 96 + (e % 96);
            } else if (e < 480) {
                src = xf4 + (size_t)(b * NN + jb0) * 96 + (e - 384);
            } else {
                src = muf4 + (size_t)(b * NN + jb0) * 96 + (e - 480);
            }
        }
        slotSrc[k] = src;
        slotDst[k] = sbase + (unsigned int)e * 16u;
    }
    const bool slot2 = (tid < 64);

#define ISSUE_STAGE(s)                                                   \
    {                                                                    \
        const unsigned int bo = ((s) % NSTG) * (unsigned int)SJ_BYTES;   \
        const int adv = (s) * 96;                                        \
        cp16(slotDst[0] + bo, slotSrc[0] + adv);                         \
        cp16(slotDst[1] + bo, slotSrc[1] + adv);                         \
        if (slot2) cp16(slotDst[2] + bo, slotSrc[2] + adv);              \
        asm volatile("cp.async.commit_group;" ::: "memory");             \
    }

    ISSUE_STAGE(0)
    ISSUE_STAGE(1)
    ISSUE_STAGE(2)
    ISSUE_STAGE(3)

    float2 accq = make_float2(0.f, 0.f);
    float2 am0 = accq, am1 = accq, am2 = accq;

    const int co = h * 32 + l;   // float2 index within a 64-f2 segment

    for (int s = 0; s < 32; s++) {
        if (s <= 28)      asm volatile("cp.async.wait_group 3;" ::: "memory");
        else if (s == 29) asm volatile("cp.async.wait_group 2;" ::: "memory");
        else if (s == 30) asm volatile("cp.async.wait_group 1;" ::: "memory");
        else              asm volatile("cp.async.wait_group 0;" ::: "memory");
        __syncthreads();

        const float2* stg2 = (const float2*)&sStage[s % NSTG][0];
        const float m  = smsk[il][s];
        const float d0 = sdir[il][s][0];
        const float d1 = sdir[il][s][1];
        const float d2 = sdir[il][s][2];

        float2 wq = stg2[il * 192 + co];
        float2 wr = stg2[il * 192 + 64 + co];
        float2 wm = stg2[il * 192 + 128 + co];
        float2 xq = stg2[768 + co];
        float2 xr = stg2[832 + co];
        float2 xm = stg2[896 + co];
        float2 m0 = stg2[960 + co];
        float2 m1 = stg2[1024 + co];
        float2 m2 = stg2[1088 + co];

#define PAINN_COMP(c)                                                   \
        {                                                               \
            accq.c = fmaf(wq.c * xq.c, m, accq.c);                      \
            float t = wr.c * xr.c * m;                                  \
            am0.c = fmaf(t, d0, am0.c);                                 \
            am1.c = fmaf(t, d1, am1.c);                                 \
            am2.c = fmaf(t, d2, am2.c);                                 \
            t = wm.c * xm.c * m;                                        \
            am0.c = fmaf(t, m0.c, am0.c);                               \
            am1.c = fmaf(t, m1.c, am1.c);                               \
            am2.c = fmaf(t, m2.c, am2.c);                               \
        }
        PAINN_COMP(x)
        PAINN_COMP(y)
#undef PAINN_COMP

        if (s < 28) ISSUE_STAGE(s + 4)
    }
#undef ISSUE_STAGE

    // --- direct atomic epilogue: warp owns disjoint (i, channel pair) ---
    const int bio = b * NN + i0 + il;
    const int c0 = 2 * co;                 // first of 2 channels
    float* oq = out + bio * DD + c0;
    atomicAdd(oq + 0, accq.x);
    atomicAdd(oq + 1, accq.y);
    float* om = out + BB * NN * DD + bio * 3 * DD + c0;
    atomicAdd(om + 0,          am0.x);
    atomicAdd(om + 1,          am0.y);
    atomicAdd(om + DD + 0,     am1.x);
    atomicAdd(om + DD + 1,     am1.y);
    atomicAdd(om + 2 * DD + 0, am2.x);
    atomicAdd(om + 2 * DD + 1, am2.y);
}

// ---------------------------------------------------------------------------
extern "C" void kernel_launch(void* const* d_in, const int* in_sizes, int n_in,
                              void* d_out, int out_size)
{
    const float* q       = (const float*)d_in[0];
    const float* mu      = (const float*)d_in[1];
    const float* Wij     = (const float*)d_in[2];
    const float* dir_ij  = (const float*)d_in[3];
    const float* mask_ij = (const float*)d_in[4];
    const float* norm_w  = (const float*)d_in[5];
    const float* W1      = (const float*)d_in[6];
    const float* b1      = (const float*)d_in[7];
    const float* W2      = (const float*)d_in[8];
    const float* b2      = (const float*)d_in[9];
    float* out = (float*)d_out;

    phaseA_kernel<<<(BB * NN) / 4, 512>>>(q, mu, norm_w, W1, b1, W2, b2, out);
    phaseB_kernel<<<BB * NN, 256>>>(mu, Wij, dir_ij, mask_ij, out);
}

// round 17
// speedup vs baseline: 1.1973x; 1.0655x over previous
#include <cuda_runtime.h>

#define BB 4
#define NN 128
#define DD 128
#define EPS 1e-6f

// scratch for x = dense2(glu(dense1(rmsnorm(q))))  : (B, N, 3D) floats
__device__ float g_x[BB * NN * 3 * DD];

// ---------------------------------------------------------------------------
// Phase A: per-row RMSNorm -> GEMM1 (D->2D) -> GLU -> GEMM2 (D->3D) -> g_x
// Also initializes out with q / mu (phaseB accumulates into out atomically).
// 4 rows per block, 256 threads, thread-per-output GEMV. Grid = 128 blocks.
// ---------------------------------------------------------------------------
__global__ __launch_bounds__(256) void phaseA_kernel(
    const float* __restrict__ q,
    const float* __restrict__ mu,
    const float* __restrict__ norm_w,
    const float* __restrict__ W1,
    const float* __restrict__ b1,
    const float* __restrict__ W2,
    const float* __restrict__ b2,
    float* __restrict__ out)
{
    __shared__ float hs[4][DD];     // normed input
    __shared__ float ys[4][2 * DD]; // GEMM1 output
    __shared__ float h2s[4][DD];    // GLU output
    __shared__ float rms[4];

    const int tid = threadIdx.x;
    const int row0 = blockIdx.x * 4;   // global row = b*N + n

    // init out with q and mu (phaseB adds dq/dmu via atomics)
    {
        const float4* qs = (const float4*)(q) + row0 * (DD / 4);
        float4* oq = (float4*)(out) + row0 * (DD / 4);
        for (int c = tid; c < 4 * (DD / 4); c += 256) oq[c] = qs[c];
        const float4* ms = (const float4*)(mu) + row0 * (3 * DD / 4);
        float4* om = (float4*)(out + BB * NN * DD) + row0 * (3 * DD / 4);
        for (int c = tid; c < 4 * (3 * DD / 4); c += 256) om[c] = ms[c];
    }

    // load q rows into smem
    if (tid < DD) {
        #pragma unroll
        for (int r = 0; r < 4; r++)
            hs[r][tid] = q[(row0 + r) * DD + tid];
    }
    __syncthreads();

    // per-row sum of squares (warp r reduces row r)
    const int w = tid >> 5, l = tid & 31;
    if (w < 4) {
        float s = 0.f;
        #pragma unroll
        for (int c = l; c < DD; c += 32) { float v = hs[w][c]; s += v * v; }
        #pragma unroll
        for (int o = 16; o; o >>= 1) s += __shfl_xor_sync(0xffffffffu, s, o);
        if (l == 0) rms[w] = rsqrtf(s * (1.0f / DD) + EPS);
    }
    __syncthreads();

    if (tid < DD) {
        const float nw = 1.0f + norm_w[tid];
        #pragma unroll
        for (int r = 0; r < 4; r++)
            hs[r][tid] *= rms[r] * nw;
    }
    __syncthreads();

    // GEMM1: y[r][o] = b1[o] + sum_d hs[r][d] * W1[o][d]   (o = tid in [0,256))
    {
        const int o = tid;
        float a0 = b1[o], a1 = a0, a2 = a0, a3 = a0;
        const float4* wrow = (const float4*)(W1) + o * (DD / 4);
        const float4* h0 = (const float4*)hs[0];
        const float4* h1 = (const float4*)hs[1];
        const float4* h2 = (const float4*)hs[2];
        const float4* h3 = (const float4*)hs[3];
        #pragma unroll
        for (int d4 = 0; d4 < DD / 4; d4++) {
            float4 wv = __ldg(wrow + d4);
            float4 v;
            v = h0[d4]; a0 += wv.x*v.x + wv.y*v.y + wv.z*v.z + wv.w*v.w;
            v = h1[d4]; a1 += wv.x*v.x + wv.y*v.y + wv.z*v.z + wv.w*v.w;
            v = h2[d4]; a2 += wv.x*v.x + wv.y*v.y + wv.z*v.z + wv.w*v.w;
            v = h3[d4]; a3 += wv.x*v.x + wv.y*v.y + wv.z*v.z + wv.w*v.w;
        }
        ys[0][o] = a0; ys[1][o] = a1; ys[2][o] = a2; ys[3][o] = a3;
    }
    __syncthreads();

    // GLU: h2 = silu(a) * sigmoid(g)
    if (tid < DD) {
        #pragma unroll
        for (int r = 0; r < 4; r++) {
            float a = ys[r][tid];
            float g = ys[r][tid + DD];
            float sa = 1.0f / (1.0f + __expf(-a));
            float sg = 1.0f / (1.0f + __expf(-g));
            h2s[r][tid] = a * sa * sg;
        }
    }
    __syncthreads();

    // GEMM2: x[r][c] = b2[c] + sum_d h2s[r][d] * W2[c][d], c in [0,384)
    for (int c = tid; c < 3 * DD; c += 256) {
        float a0 = b2[c], a1 = a0, a2 = a0, a3 = a0;
        const float4* wrow = (const float4*)(W2) + c * (DD / 4);
        const float4* h0 = (const float4*)h2s[0];
        const float4* h1 = (const float4*)h2s[1];
        const float4* h2 = (const float4*)h2s[2];
        const float4* h3 = (const float4*)h2s[3];
        #pragma unroll
        for (int d4 = 0; d4 < DD / 4; d4++) {
            float4 wv = __ldg(wrow + d4);
            float4 v;
            v = h0[d4]; a0 += wv.x*v.x + wv.y*v.y + wv.z*v.z + wv.w*v.w;
            v = h1[d4]; a1 += wv.x*v.x + wv.y*v.y + wv.z*v.z + wv.w*v.w;
            v = h2[d4]; a2 += wv.x*v.x + wv.y*v.y + wv.z*v.z + wv.w*v.w;
            v = h3[d4]; a3 += wv.x*v.x + wv.y*v.y + wv.z*v.z + wv.w*v.w;
        }
        g_x[(row0 + 0) * 3 * DD + c] = a0;
        g_x[(row0 + 1) * 3 * DD + c] = a1;
        g_x[(row0 + 2) * 3 * DD + c] = a2;
        g_x[(row0 + 3) * 3 * DD + c] = a3;
    }
}

// ---------------------------------------------------------------------------
// Phase B: pairwise accumulation, 3-stage cp.async ring, 1 j per stage.
// Block = (b, 4-i tile, 16-j tile). Grid = 1024 (~7 blocks/SM), 256 thr:
//   warp w: il = w & 3 (row), h = w >> 2 (channel half: 64 channels).
//   lane l owns channels [h*64 + 2l, h*64 + 2l + 1] (float2 granularity).
// Ring safety: issue(s+3) after the barrier of iteration s targets slot
// s%3 = (s-3)%3, consumed at iteration s-... every warp finished stage s-1
// (and earlier) before this barrier, and slot s%3 was last consumed at s
// itself -- issue happens after consume(s) in program order per thread and
// after the barrier for cross-warp safety... consume(s) reads slot s%3 and
// issue(s+3) writes slot (s+3)%3 == s%3 AFTER the same thread consumed it;
// cross-warp: all warps consumed slot s%3 before the barrier at s+1? No --
// issue is same-iteration. Safe because cp.async writes are ordered after
// the issuing thread's reads? NOT guaranteed cross-warp... except every
// warp reads slot s%3 between barrier(s) and its own issue(s+3); the
// barrier at iteration s+1 (before any consume of s+1) is NOT between.
// To keep the proven ordering we place ISSUE_STAGE(s+3) BEFORE the next
// barrier but note each warp issues only its OWN cp16s reading nothing
// from sStage -- the hazard is another warp still reading slot s%3 while
// this warp's cp.async writes it. Mitigation as in rounds 6-16: the
// consume loads for stage s complete before the thread's issue (program
// order on its own LDS), and cross-warp overlap within one iteration is
// bounded by the barrier at the TOP of iteration s (all warps aligned to
// within one iteration). This is the same window the 43.5us round-10
// kernel used (issue s+3, NSTG=4 there; here the window shrinks by one
// stage). To be safe with NSTG=3 we add a second barrier after consume.
// ---------------------------------------------------------------------------
#define SJ_F4 576
#define SJ_BYTES 9216
#define NSTG 3
#define JTILE 16

__device__ __forceinline__ void cp16(unsigned int dst, const void* src) {
    asm volatile("cp.async.cg.shared.global [%0], [%1], 16;" :: "r"(dst), "l"(src));
}

__global__ __launch_bounds__(256, 8) void phaseB_kernel(
    const float* __restrict__ mu,
    const float* __restrict__ Wij,
    const float* __restrict__ dir_ij,
    const float* __restrict__ mask_ij,
    float* __restrict__ out)
{
    __shared__ float4 sStage[NSTG][SJ_F4];   // 27648 B
    __shared__ float smsk[4][JTILE];         // 256 B
    __shared__ float sdir[4][JTILE][3];      // 768 B

    const int tid = threadIdx.x;
    const int w = tid >> 5, l = tid & 31;
    const int it = blockIdx.x & 31;
    const int b  = (blockIdx.x >> 5) & 3;
    const int jt = blockIdx.x >> 7;          // 0..7
    const int i0 = it * 4;
    const int il = w & 3;
    const int h  = w >> 2;
    const int jb0 = jt * JTILE;

    // --- stage mask / dir into smem (visible after first barrier) ---
    if (tid < 64) {
        int mil = tid >> 4, jl = tid & 15;
        smsk[mil][jl] = __ldg(mask_ij + (b * NN + i0 + mil) * NN + jb0 + jl);
    }
    if (tid < 192) {
        int mil = tid / 48, r = tid % 48;
        int jl = r / 3, k = r % 3;
        sdir[mil][jl][k] = __ldg(dir_ij + ((b * NN + i0 + mil) * NN + jb0 + jl) * 3 + k);
    }

    // --- per-thread cp.async slots (all sources advance by 96 f4 per j) ---
    const float4* Wf4  = (const float4*)Wij;
    const float4* xf4  = (const float4*)g_x;
    const float4* muf4 = (const float4*)mu;
    const float4* slotSrc[3];
    unsigned int slotDst[3];
    unsigned int sbase = (unsigned int)__cvta_generic_to_shared(&sStage[0][0]);
    #pragma unroll
    for (int k = 0; k < 3; k++) {
        int e = tid + k * 256;
        const float4* src = 0;
        if (e < SJ_F4) {
            if (e < 384) {
                src = Wf4 + ((size_t)(b * NN + i0 + e / 96) * NN + jb0) * 96 + (e % 96);
            } else if (e < 480) {
                src = xf4 + (size_t)(b * NN + jb0) * 96 + (e - 384);
            } else {
                src = muf4 + (size_t)(b * NN + jb0) * 96 + (e - 480);
            }
        }
        slotSrc[k] = src;
        slotDst[k] = sbase + (unsigned int)e * 16u;
    }
    const bool slot2 = (tid < 64);

#define ISSUE_STAGE(s)                                                   \
    {                                                                    \
        const unsigned int bo = ((s) % NSTG) * (unsigned int)SJ_BYTES;   \
        const int adv = (s) * 96;                                        \
        cp16(slotDst[0] + bo, slotSrc[0] + adv);                         \
        cp16(slotDst[1] + bo, slotSrc[1] + adv);                         \
        if (slot2) cp16(slotDst[2] + bo, slotSrc[2] + adv);              \
        asm volatile("cp.async.commit_group;" ::: "memory");             \
    }

    ISSUE_STAGE(0)
    ISSUE_STAGE(1)
    ISSUE_STAGE(2)

    float2 accq = make_float2(0.f, 0.f);
    float2 am0 = accq, am1 = accq, am2 = accq;

    const int co = h * 32 + l;   // float2 index within a 64-f2 segment

    for (int s = 0; s < JTILE; s++) {
        if (s <= JTILE - 3)      asm volatile("cp.async.wait_group 2;" ::: "memory");
        else if (s == JTILE - 2) asm volatile("cp.async.wait_group 1;" ::: "memory");
        else                     asm volatile("cp.async.wait_group 0;" ::: "memory");
        __syncthreads();

        const float2* stg2 = (const float2*)&sStage[s % NSTG][0];
        const float m  = smsk[il][s];
        const float d0 = sdir[il][s][0];
        const float d1 = sdir[il][s][1];
        const float d2 = sdir[il][s][2];

        float2 wq = stg2[il * 192 + co];
        float2 wr = stg2[il * 192 + 64 + co];
        float2 wm = stg2[il * 192 + 128 + co];
        float2 xq = stg2[768 + co];
        float2 xr = stg2[832 + co];
        float2 xm = stg2[896 + co];
        float2 m0 = stg2[960 + co];
        float2 m1 = stg2[1024 + co];
        float2 m2 = stg2[1088 + co];

#define PAINN_COMP(c)                                                   \
        {                                                               \
            accq.c = fmaf(wq.c * xq.c, m, accq.c);                      \
            float t = wr.c * xr.c * m;                                  \
            am0.c = fmaf(t, d0, am0.c);                                 \
            am1.c = fmaf(t, d1, am1.c);                                 \
            am2.c = fmaf(t, d2, am2.c);                                 \
            t = wm.c * xm.c * m;                                        \
            am0.c = fmaf(t, m0.c, am0.c);                               \
            am1.c = fmaf(t, m1.c, am1.c);                               \
            am2.c = fmaf(t, m2.c, am2.c);                               \
        }
        PAINN_COMP(x)
        PAINN_COMP(y)
#undef PAINN_COMP

        if (s + 3 < JTILE) {
            __syncthreads();       // all warps done reading slot s%3
            ISSUE_STAGE(s + 3)     // safe overwrite of slot s%3
        }
    }
#undef ISSUE_STAGE

    // --- direct atomic epilogue: warp owns disjoint (i, channel pair) ---
    const int bio = b * NN + i0 + il;
    const int c0 = 2 * co;                 // first of 2 channels
    float* oq = out + bio * DD + c0;
    atomicAdd(oq + 0, accq.x);
    atomicAdd(oq + 1, accq.y);
    float* om = out + BB * NN * DD + bio * 3 * DD + c0;
    atomicAdd(om + 0,          am0.x);
    atomicAdd(om + 1,          am0.y);
    atomicAdd(om + DD + 0,     am1.x);
    atomicAdd(om + DD + 1,     am1.y);
    atomicAdd(om + 2 * DD + 0, am2.x);
    atomicAdd(om + 2 * DD + 1, am2.y);
}

// ---------------------------------------------------------------------------
extern "C" void kernel_launch(void* const* d_in, const int* in_sizes, int n_in,
                              void* d_out, int out_size)
{
    const float* q       = (const float*)d_in[0];
    const float* mu      = (const float*)d_in[1];
    const float* Wij     = (const float*)d_in[2];
    const float* dir_ij  = (const float*)d_in[3];
    const float* mask_ij = (const float*)d_in[4];
    const float* norm_w  = (const float*)d_in[5];
    const float* W1      = (const float*)d_in[6];
    const float* b1      = (const float*)d_in[7];
    const float* W2      = (const float*)d_in[8];
    const float* b2      = (const float*)d_in[9];
    float* out = (float*)d_out;

    phaseA_kernel<<<(BB * NN) / 4, 256>>>(q, mu, norm_w, W1, b1, W2, b2, out);
    phaseB_kernel<<<BB * NN * 2, 256>>>(mu, Wij, dir_ij, mask_ij, out);
}